// round 8
// baseline (speedup 1.0000x reference)
#include <cuda_runtime.h>
#include <cstdint>

#define HIDDEN  20
#define N_MID   8

#define CB     0.5f
#define CC     0.5f
#define CSIGMA 1.0f
#define CBF    0.5f
#define CCF    0.9f

typedef unsigned int u32;

// ---------------- bf16 split/pack helpers ----------------
// hi = top-16-bit truncation of v (exact bf16), lo = rn_bf16(v - hi).
// Packs (v0 -> low half, v1 -> high half) matching mma fragment order.
__device__ __forceinline__ void split_pack(float v0, float v1, u32& hi, u32& lo) {
    const u32 i0 = __float_as_uint(v0), i1 = __float_as_uint(v1);
    hi = __byte_perm(i0, i1, 0x7632);
    const float l0 = v0 - __uint_as_float(i0 & 0xFFFF0000u);
    const float l1 = v1 - __uint_as_float(i1 & 0xFFFF0000u);
    asm("cvt.rn.bf16x2.f32 %0, %1, %2;" : "=r"(lo) : "f"(l1), "f"(l0));
}

// m16n8k16 row.col bf16 MMA, fp32 accumulate in place.
__device__ __forceinline__ void mma_bf16(float d[4], const u32 a[4], u32 b0, u32 b1) {
    asm volatile(
        "mma.sync.aligned.m16n8k16.row.col.f32.bf16.bf16.f32 "
        "{%0,%1,%2,%3}, {%4,%5,%6,%7}, {%8,%9}, {%0,%1,%2,%3};"
        : "+f"(d[0]), "+f"(d[1]), "+f"(d[2]), "+f"(d[3])
        : "r"(a[0]), "r"(a[1]), "r"(a[2]), "r"(a[3]), "r"(b0), "r"(b1));
}

// accurate tanh (EX2 + approx rcp, rel err ~2^-22)
__device__ __forceinline__ float tanh_acc(float z) {
    float az = fabsf(z);
    float e  = __expf(-2.0f * az);
    float r  = __fdividef(1.0f - e, 1.0f + e);
    return copysignf(r, z);
}

__global__ __launch_bounds__(128)
void pde_mma_kernel(const float* __restrict__ x,
                    const float* __restrict__ W_in,
                    const float* __restrict__ b_in,
                    const float* __restrict__ W_mid,
                    const float* __restrict__ b_mid,
                    const float* __restrict__ W_out,
                    const float* __restrict__ b_out,
                    float* __restrict__ out,
                    int n)
{
    // Per-lane B fragments: [layer][chunk i4(6)][lane(32)][4 u32] = 24 KB
    __shared__ u32  sBf[N_MID * 6 * 32 * 4];
    __shared__ float sWin[HIDDEN * 2];
    __shared__ float sbin[HIDDEN];
    __shared__ float sWout[24];
    __shared__ float sbout;

    const int tid = threadIdx.x;

    // ---------- prep: build split-bf16 B fragments ----------
    // idx = kt*12 + nt*4 + sp*2 + r  (kt: K-tile, nt: N-tile, sp: hi/lo, r: reg)
    for (int e = tid; e < N_MID * 32 * 24; e += blockDim.x) {
        const int layer  = e / 768;
        const int rem    = e - layer * 768;
        const int lane_e = rem / 24;
        const int idx    = rem % 24;
        const int r  = idx & 1;
        const int sp = (idx >> 1) & 1;
        const int nt = (idx >> 2) % 3;
        const int kt = idx / 12;
        const int c  = lane_e & 3;
        const int g  = lane_e >> 2;
        const int nn = nt * 8 + g;
        const int k0 = kt * 16 + 2 * c + r * 8;

        float v0 = 0.0f, v1 = 0.0f;
        if (nn < HIDDEN) {
            const int k1 = k0 + 1;
            if (k0 < HIDDEN)       v0 = W_mid[layer * 400 + nn * 20 + k0];
            else if (k0 == HIDDEN) v0 = b_mid[layer * 20 + nn];
            if (k1 < HIDDEN)       v1 = W_mid[layer * 400 + nn * 20 + k1];
            else if (k1 == HIDDEN) v1 = b_mid[layer * 20 + nn];
        }
        u32 hi, lo;
        split_pack(v0, v1, hi, lo);
        sBf[layer * 768 + (idx >> 2) * 128 + lane_e * 4 + (idx & 3)] = sp ? lo : hi;
    }
    if (tid < HIDDEN * 2) sWin[tid] = W_in[tid];
    if (tid < HIDDEN)     sbin[tid] = b_in[tid];
    if (tid < 24)         sWout[tid] = (tid < HIDDEN) ? W_out[tid] : 0.0f;
    if (tid == 0)         sbout = b_out[0];
    __syncthreads();

    const int lane = tid & 31;
    const int wid  = tid >> 5;
    const int c    = lane & 3;
    const int g    = lane >> 2;
    const int gwid = blockIdx.x * (blockDim.x >> 5) + wid;
    const int warp_base = gwid * 8;       // 8 points per warp
    if (warp_base >= n) return;
    const int p = warp_base + g;

    const float2 xi = reinterpret_cast<const float2*>(x)[p];
    const float t = xi.x, xs = xi.y;

    // D frags: DY = [z rows | zu rows], DX = [zv | zw], per N-tile 4 floats.
    float DY[12], DX[12];
    // A frags: [Mtile(0=Y,1=X)][Ktile(2)][reg(4)], hi + lo splits.
    u32 Ah[2][2][4], Al[2][2][4];

    // ---------- input layer: fill D with pre-activations ----------
    #pragma unroll
    for (int i = 0; i < 6; i++) {
        const int nt = i >> 1;
        const int neuron = nt * 8 + 2 * c + (i & 1);
        float z = 0.0f, w0 = 0.0f, w1 = 0.0f;
        if (neuron < HIDDEN) {
            w0 = sWin[2 * neuron];
            w1 = sWin[2 * neuron + 1];
            z  = fmaf(w0, t, fmaf(w1, xs, sbin[neuron]));
        }
        DY[nt * 4 + (i & 1)]     = z;      // z
        DY[nt * 4 + 2 + (i & 1)] = w0;     // zu
        DX[nt * 4 + (i & 1)]     = w1;     // zv
        DX[nt * 4 + 2 + (i & 1)] = 0.0f;   // zw
    }

    float nh[6], nu[6], nv[6], nw[6];
    float f = 0.0f, fu = 0.0f, fv = 0.0f, fw = 0.0f;

    #pragma unroll 1
    for (int l = 0; l <= N_MID; l++) {
        if (l > 0) {
            // ---- load this layer's B fragments (6x LDS.128, conflict-free) ----
            u32 B[24];
            #pragma unroll
            for (int i4 = 0; i4 < 6; i4++) {
                const uint4 q = *reinterpret_cast<const uint4*>(
                    &sBf[(l - 1) * 768 + i4 * 128 + lane * 4]);
                B[i4 * 4 + 0] = q.x; B[i4 * 4 + 1] = q.y;
                B[i4 * 4 + 2] = q.z; B[i4 * 4 + 3] = q.w;
            }
            // ---- 36 MMAs: D[m][nt] = sum_kt (AhBh + AhBl + AlBh) ----
            #pragma unroll
            for (int m = 0; m < 2; m++) {
                #pragma unroll
                for (int nt = 0; nt < 3; nt++) {
                    float* d = (m ? DX : DY) + nt * 4;
                    d[0] = d[1] = d[2] = d[3] = 0.0f;
                    #pragma unroll
                    for (int kt = 0; kt < 2; kt++) {
                        const int bh = kt * 12 + nt * 4;        // sp=0
                        const int bl = bh + 2;                  // sp=1
                        mma_bf16(d, Ah[m][kt], B[bh], B[bh + 1]);
                        mma_bf16(d, Ah[m][kt], B[bl], B[bl + 1]);
                        mma_bf16(d, Al[m][kt], B[bh], B[bh + 1]);
                    }
                }
            }
        }

        // ---- elementwise tanh chain (fully thread-local) ----
        #pragma unroll
        for (int nt = 0; nt < 3; nt++) {
            #pragma unroll
            for (int i = 0; i < 2; i++) {
                const float z  = DY[nt * 4 + i];
                const float zu = DY[nt * 4 + 2 + i];
                const float zv = DX[nt * 4 + i];
                const float zw = DX[nt * 4 + 2 + i];
                const float a = tanh_acc(z);
                const float d = fmaf(-a, a, 1.0f);
                const int o = nt * 2 + i;
                nh[o] = a;
                nu[o] = d * zu;
                nv[o] = d * zv;
                nw[o] = fmaf(d, zw, -2.0f * a * nv[o] * zv);
            }
        }

        if (l < N_MID) {
            // ---- build next-layer A fragments (split-bf16) ----
            split_pack(nh[0], nh[1], Ah[0][0][0], Al[0][0][0]);
            split_pack(nu[0], nu[1], Ah[0][0][1], Al[0][0][1]);
            split_pack(nh[2], nh[3], Ah[0][0][2], Al[0][0][2]);
            split_pack(nu[2], nu[3], Ah[0][0][3], Al[0][0][3]);
            split_pack(nh[4], nh[5], Ah[0][1][0], Al[0][1][0]);
            split_pack(nu[4], nu[5], Ah[0][1][1], Al[0][1][1]);
            if (c == 2) {                       // bias column k=20: h rows get 1.0
                Ah[0][1][0] = 0x00003F80u; Al[0][1][0] = 0u;
            }
            Ah[0][1][2] = Ah[0][1][3] = Al[0][1][2] = Al[0][1][3] = 0u;

            split_pack(nv[0], nv[1], Ah[1][0][0], Al[1][0][0]);
            split_pack(nw[0], nw[1], Ah[1][0][1], Al[1][0][1]);
            split_pack(nv[2], nv[3], Ah[1][0][2], Al[1][0][2]);
            split_pack(nw[2], nw[3], Ah[1][0][3], Al[1][0][3]);
            split_pack(nv[4], nv[5], Ah[1][1][0], Al[1][1][0]);
            split_pack(nw[4], nw[5], Ah[1][1][1], Al[1][1][1]);
            Ah[1][1][2] = Ah[1][1][3] = Al[1][1][2] = Al[1][1][3] = 0u;
        } else {
            // ---- output layer: partial dots, reduce across the 4-lane group ----
            #pragma unroll
            for (int i = 0; i < 6; i++) {
                const int neuron = (i >> 1) * 8 + 2 * c + (i & 1);
                const float wo = sWout[neuron];
                f  = fmaf(wo, nh[i], f);
                fu = fmaf(wo, nu[i], fu);
                fv = fmaf(wo, nv[i], fv);
                fw = fmaf(wo, nw[i], fw);
            }
        }
    }

    #pragma unroll
    for (int ofs = 1; ofs <= 2; ofs <<= 1) {
        f  += __shfl_xor_sync(0xFFFFFFFFu, f,  ofs);
        fu += __shfl_xor_sync(0xFFFFFFFFu, fu, ofs);
        fv += __shfl_xor_sync(0xFFFFFFFFu, fv, ofs);
        fw += __shfl_xor_sync(0xFFFFFFFFu, fw, ofs);
    }

    if (c == 0) {
        f += sbout;
        const float pde = CBF * xs * xs
                        + fu
                        + 0.5f * CSIGMA * CSIGMA * fw
                        + CB * xs * fv
                        - (CC * CC / (4.0f * CCF)) * fv * fv;
        out[p]     = f;
        out[n + p] = pde;
    }
}

extern "C" void kernel_launch(void* const* d_in, const int* in_sizes, int n_in,
                              void* d_out, int out_size)
{
    const float* x     = (const float*)d_in[0];
    const float* W_in  = (const float*)d_in[1];
    const float* b_in  = (const float*)d_in[2];
    const float* W_mid = (const float*)d_in[3];
    const float* b_mid = (const float*)d_in[4];
    const float* W_out = (const float*)d_in[5];
    const float* b_out = (const float*)d_in[6];
    float* out = (float*)d_out;

    const int n = in_sizes[0] / 2;          // x is (N, 2)
    const int threads = 128;                // 4 warps -> 32 points per CTA
    const int blocks  = (n + 31) / 32;
    pde_mma_kernel<<<blocks, threads>>>(x, W_in, b_in, W_mid, b_mid,
                                        W_out, b_out, out, n);
}

// round 9
// speedup vs baseline: 1.8566x; 1.8566x over previous
#include <cuda_runtime.h>

#define HIDDEN  20
#define N_MID   8

#define CB     0.5f
#define CC     0.5f
#define CSIGMA 1.0f
#define CBF    0.5f
#define CCF    0.9f

typedef unsigned long long ull;

// ---------------- packed f32x2 helpers (Blackwell) ----------------
__device__ __forceinline__ ull pack2(float lo, float hi) {
    ull r;
    asm("mov.b64 %0, {%1, %2};" : "=l"(r) : "f"(lo), "f"(hi));
    return r;
}
__device__ __forceinline__ void unpack2(ull p, float& lo, float& hi) {
    asm("mov.b64 {%0, %1}, %2;" : "=f"(lo), "=f"(hi) : "l"(p));
}
__device__ __forceinline__ ull fma2(ull a, ull b, ull c) {
    ull r;
    asm("fma.rn.f32x2 %0, %1, %2, %3;" : "=l"(r) : "l"(a), "l"(b), "l"(c));
    return r;
}
__device__ __forceinline__ ull add2(ull a, ull b) {
    ull r;
    asm("add.rn.f32x2 %0, %1, %2;" : "=l"(r) : "l"(a), "l"(b));
    return r;
}

// Hardware tanh: single MUFU.TANH op (abs err ~2^-11). Frees ~10 fma-pipe
// cycles per neuron vs the exp/rcp construction. Precision is this round's
// experiment: estimated final rel_err 1e-4..1e-3 vs 1e-3 threshold.
__device__ __forceinline__ float tanh_fast(float z) {
    float r;
    asm("tanh.approx.f32 %0, %1;" : "=f"(r) : "f"(z));
    return r;
}

// One mid layer: (hu,vw) -> (nhu,nvw). Fully unrolled; weights via LDS.128.
__device__ __forceinline__ void mid_layer(const ull* __restrict__ Wl,
                                          const ull* __restrict__ bl,
                                          const ull hu[HIDDEN],
                                          const ull vw[HIDDEN],
                                          ull nhu[HIDDEN],
                                          ull nvw[HIDDEN])
{
    #pragma unroll
    for (int j = 0; j < HIDDEN; j++) {
        ull zhu0 = bl[j];                 // (b, 0)
        ull zvw0 = 0ull;
        ull zhu1 = 0ull;
        ull zvw1 = 0ull;
        const ulonglong2* __restrict__ Wrow =
            reinterpret_cast<const ulonglong2*>(&Wl[j * HIDDEN]);
        #pragma unroll
        for (int k2 = 0; k2 < HIDDEN / 2; k2++) {
            const ulonglong2 ww = Wrow[k2];          // LDS.128: (w_k,w_k),(w_k1,w_k1)
            const int k = 2 * k2;
            zhu0 = fma2(ww.x, hu[k],     zhu0);
            zvw0 = fma2(ww.x, vw[k],     zvw0);
            zhu1 = fma2(ww.y, hu[k + 1], zhu1);
            zvw1 = fma2(ww.y, vw[k + 1], zvw1);
        }
        const ull zhu = add2(zhu0, zhu1);
        const ull zvw = add2(zvw0, zvw1);

        float z, zu, zv, zw;
        unpack2(zhu, z, zu);
        unpack2(zvw, zv, zw);
        const float a = tanh_fast(z);
        const float d = fmaf(-a, a, 1.0f);
        const float nv = d * zv;
        nhu[j] = pack2(a, d * zu);
        nvw[j] = pack2(nv, fmaf(d, zw, -2.0f * (a * nv) * zv));
    }
}

__global__ __launch_bounds__(256, 1)
void pde_mlp_kernel(const float* __restrict__ x,
                    const float* __restrict__ W_in,
                    const float* __restrict__ b_in,
                    const float* __restrict__ W_mid,
                    const float* __restrict__ b_mid,
                    const float* __restrict__ W_out,
                    const float* __restrict__ b_out,
                    float* __restrict__ out,
                    int n)
{
    __shared__ __align__(16) ull sW2[N_MID * HIDDEN * HIDDEN];   // (w,w) pairs, 25.6 KB
    __shared__ ull sB2[N_MID * HIDDEN];                          // (b,0)
    __shared__ ull sWout2[HIDDEN];
    __shared__ float sWin[HIDDEN * 2];
    __shared__ float sbin[HIDDEN];
    __shared__ float sbout;

    const int tid = threadIdx.x;
    for (int i = tid; i < N_MID * HIDDEN * HIDDEN; i += blockDim.x) {
        const float wv = W_mid[i];
        sW2[i] = pack2(wv, wv);
    }
    for (int i = tid; i < N_MID * HIDDEN; i += blockDim.x)
        sB2[i] = pack2(b_mid[i], 0.0f);
    for (int i = tid; i < HIDDEN; i += blockDim.x) {
        const float wv = W_out[i];
        sWout2[i] = pack2(wv, wv);
        sbin[i]   = b_in[i];
    }
    for (int i = tid; i < HIDDEN * 2; i += blockDim.x) sWin[i] = W_in[i];
    if (tid == 0) sbout = b_out[0];
    __syncthreads();

    const int gid = blockIdx.x * blockDim.x + tid;
    if (gid >= n) return;

    const float2 xi = reinterpret_cast<const float2*>(x)[gid];
    const float t  = xi.x;
    const float xs = xi.y;

    // Packed forward-mode state: hu=(h,dh/dt), vw=(dh/dx,d2h/dx2); ping-pong.
    ull huA[HIDDEN], vwA[HIDDEN], huB[HIDDEN], vwB[HIDDEN];

    // ---- input layer ----
    #pragma unroll
    for (int j = 0; j < HIDDEN; j++) {
        const float w0 = sWin[2 * j];
        const float w1 = sWin[2 * j + 1];
        const float z  = fmaf(w0, t, fmaf(w1, xs, sbin[j]));
        const float a  = tanh_fast(z);
        const float d  = fmaf(-a, a, 1.0f);
        const float nv = d * w1;
        huA[j] = pack2(a, d * w0);
        vwA[j] = pack2(nv, -2.0f * (a * nv) * w1);
    }

    // ---- mid layers, ping-pong (no state copies) ----
    #pragma unroll 1
    for (int lp = 0; lp < N_MID; lp += 2) {
        mid_layer(&sW2[(lp    ) * HIDDEN * HIDDEN], &sB2[(lp    ) * HIDDEN],
                  huA, vwA, huB, vwB);
        mid_layer(&sW2[(lp + 1) * HIDDEN * HIDDEN], &sB2[(lp + 1) * HIDDEN],
                  huB, vwB, huA, vwA);
    }

    // ---- output layer (linear) ----
    ull fhu0 = pack2(sbout, 0.0f), fvw0 = 0ull;
    ull fhu1 = 0ull, fvw1 = 0ull;
    #pragma unroll
    for (int k2 = 0; k2 < HIDDEN / 2; k2++) {
        const ulonglong2 ww = reinterpret_cast<const ulonglong2*>(sWout2)[k2];
        const int k = 2 * k2;
        fhu0 = fma2(ww.x, huA[k],     fhu0);
        fvw0 = fma2(ww.x, vwA[k],     fvw0);
        fhu1 = fma2(ww.y, huA[k + 1], fhu1);
        fvw1 = fma2(ww.y, vwA[k + 1], fvw1);
    }
    float f, fu, fv, fw;
    unpack2(add2(fhu0, fhu1), f, fu);
    unpack2(add2(fvw0, fvw1), fv, fw);

    const float pde = CBF * xs * xs
                    + fu
                    + 0.5f * CSIGMA * CSIGMA * fw
                    + CB * xs * fv
                    - (CC * CC / (4.0f * CCF)) * fv * fv;

    out[gid]     = f;
    out[n + gid] = pde;
}

extern "C" void kernel_launch(void* const* d_in, const int* in_sizes, int n_in,
                              void* d_out, int out_size)
{
    const float* x     = (const float*)d_in[0];
    const float* W_in  = (const float*)d_in[1];
    const float* b_in  = (const float*)d_in[2];
    const float* W_mid = (const float*)d_in[3];
    const float* b_mid = (const float*)d_in[4];
    const float* W_out = (const float*)d_in[5];
    const float* b_out = (const float*)d_in[6];
    float* out = (float*)d_out;

    const int n = in_sizes[0] / 2;   // x is (N, 2)
    const int threads = 256;
    const int blocks  = (n + threads - 1) / threads;
    pde_mlp_kernel<<<blocks, threads>>>(x, W_in, b_in, W_mid, b_mid,
                                        W_out, b_out, out, n);
}

// round 11
// speedup vs baseline: 1.9291x; 1.0390x over previous
#include <cuda_runtime.h>

#define HIDDEN  20
#define N_MID   8

#define CB     0.5f
#define CC     0.5f
#define CSIGMA 1.0f
#define CBF    0.5f
#define CCF    0.9f

typedef unsigned long long ull;

// ---------------- packed f32x2 helpers (Blackwell) ----------------
__device__ __forceinline__ ull pack2(float lo, float hi) {
    ull r;
    asm("mov.b64 %0, {%1, %2};" : "=l"(r) : "f"(lo), "f"(hi));
    return r;
}
__device__ __forceinline__ void unpack2(ull p, float& lo, float& hi) {
    asm("mov.b64 {%0, %1}, %2;" : "=f"(lo), "=f"(hi) : "l"(p));
}
__device__ __forceinline__ ull fma2(ull a, ull b, ull c) {
    ull r;
    asm("fma.rn.f32x2 %0, %1, %2, %3;" : "=l"(r) : "l"(a), "l"(b), "l"(c));
    return r;
}
__device__ __forceinline__ ull add2(ull a, ull b) {
    ull r;
    asm("add.rn.f32x2 %0, %1, %2;" : "=l"(r) : "l"(a), "l"(b));
    return r;
}

// Hardware tanh: single MUFU.TANH (abs err ~2^-11; final rel_err ~2e-5, safe).
__device__ __forceinline__ float tanh_fast(float z) {
    float r;
    asm("tanh.approx.f32 %0, %1;" : "=f"(r) : "f"(z));
    return r;
}

// One mid layer: (hu,vw) -> (nhu,nvw).
// Single accumulator pair per stream (bank-bound regime: 2 chains x rt3 =
// 6 cyc/step > lat 5, so no ILP loss) — deletes the 2 add2/neuron of R3.
__device__ __forceinline__ void mid_layer(const ull* __restrict__ Wl,
                                          const ull* __restrict__ bl,
                                          const ull hu[HIDDEN],
                                          const ull vw[HIDDEN],
                                          ull nhu[HIDDEN],
                                          ull nvw[HIDDEN])
{
    #pragma unroll
    for (int j = 0; j < HIDDEN; j++) {
        ull zhu = bl[j];                  // (b, 0)
        ull zvw = 0ull;
        const ulonglong2* __restrict__ Wrow =
            reinterpret_cast<const ulonglong2*>(&Wl[j * HIDDEN]);
        #pragma unroll
        for (int k2 = 0; k2 < HIDDEN / 2; k2++) {
            const ulonglong2 ww = Wrow[k2];          // LDS.128: (w_k,w_k),(w_k1,w_k1)
            const int k = 2 * k2;
            zhu = fma2(ww.x, hu[k],     zhu);
            zvw = fma2(ww.x, vw[k],     zvw);
            zhu = fma2(ww.y, hu[k + 1], zhu);
            zvw = fma2(ww.y, vw[k + 1], zvw);
        }
        float z, zu, zv, zw;
        unpack2(zhu, z, zu);
        unpack2(zvw, zv, zw);
        const float a  = tanh_fast(z);
        const float d  = fmaf(-a, a, 1.0f);
        const float nv = d * zv;
        const float t  = (-2.0f) * (a * nv);   // FMUL-imm (rt=1) + FMUL
        nhu[j] = pack2(a, d * zu);
        nvw[j] = pack2(nv, fmaf(t, zv, d * zw));
    }
}

__global__ __launch_bounds__(256, 1)
void pde_mlp_kernel(const float* __restrict__ x,
                    const float* __restrict__ W_in,
                    const float* __restrict__ b_in,
                    const float* __restrict__ W_mid,
                    const float* __restrict__ b_mid,
                    const float* __restrict__ W_out,
                    const float* __restrict__ b_out,
                    float* __restrict__ out,
                    int n)
{
    __shared__ __align__(16) ull sW2[N_MID * HIDDEN * HIDDEN];   // (w,w) pairs, 25.6 KB
    __shared__ ull sB2[N_MID * HIDDEN];                          // (b,0)
    __shared__ __align__(16) ull sWout2[HIDDEN];
    __shared__ float sWin[HIDDEN * 2];
    __shared__ float sbin[HIDDEN];
    __shared__ float sbout;

    const int tid = threadIdx.x;
    for (int i = tid; i < N_MID * HIDDEN * HIDDEN; i += blockDim.x) {
        const float wv = W_mid[i];
        sW2[i] = pack2(wv, wv);
    }
    for (int i = tid; i < N_MID * HIDDEN; i += blockDim.x)
        sB2[i] = pack2(b_mid[i], 0.0f);
    for (int i = tid; i < HIDDEN; i += blockDim.x) {
        const float wv = W_out[i];
        sWout2[i] = pack2(wv, wv);
        sbin[i]   = b_in[i];
    }
    for (int i = tid; i < HIDDEN * 2; i += blockDim.x) sWin[i] = W_in[i];
    if (tid == 0) sbout = b_out[0];
    __syncthreads();

    const int gid = blockIdx.x * blockDim.x + tid;
    if (gid >= n) return;

    const float2 xi = reinterpret_cast<const float2*>(x)[gid];
    const float t  = xi.x;
    const float xs = xi.y;

    // Packed forward-mode state: hu=(h,dh/dt), vw=(dh/dx,d2h/dx2); ping-pong.
    ull huA[HIDDEN], vwA[HIDDEN], huB[HIDDEN], vwB[HIDDEN];

    // ---- input layer ----
    #pragma unroll
    for (int j = 0; j < HIDDEN; j++) {
        const float w0 = sWin[2 * j];
        const float w1 = sWin[2 * j + 1];
        const float z  = fmaf(w0, t, fmaf(w1, xs, sbin[j]));
        const float a  = tanh_fast(z);
        const float d  = fmaf(-a, a, 1.0f);
        const float nv = d * w1;
        huA[j] = pack2(a, d * w0);
        vwA[j] = pack2(nv, (-2.0f) * (a * nv) * w1);
    }

    // ---- mid layers, ping-pong (no state copies) ----
    #pragma unroll 1
    for (int lp = 0; lp < N_MID; lp += 2) {
        mid_layer(&sW2[(lp    ) * HIDDEN * HIDDEN], &sB2[(lp    ) * HIDDEN],
                  huA, vwA, huB, vwB);
        mid_layer(&sW2[(lp + 1) * HIDDEN * HIDDEN], &sB2[(lp + 1) * HIDDEN],
                  huB, vwB, huA, vwA);
    }

    // ---- output layer (linear) ----
    ull fhu = pack2(sbout, 0.0f);
    ull fvw = 0ull;
    #pragma unroll
    for (int k2 = 0; k2 < HIDDEN / 2; k2++) {
        const ulonglong2 ww = reinterpret_cast<const ulonglong2*>(sWout2)[k2];
        const int k = 2 * k2;
        fhu = fma2(ww.x, huA[k],     fhu);
        fvw = fma2(ww.x, vwA[k],     fvw);
        fhu = fma2(ww.y, huA[k + 1], fhu);
        fvw = fma2(ww.y, vwA[k + 1], fvw);
    }
    float f, fu, fv, fw;
    unpack2(fhu, f, fu);
    unpack2(fvw, fv, fw);

    const float pde = CBF * xs * xs
                    + fu
                    + 0.5f * CSIGMA * CSIGMA * fw
                    + CB * xs * fv
                    - (CC * CC / (4.0f * CCF)) * fv * fv;

    out[gid]     = f;
    out[n + gid] = pde;
}

extern "C" void kernel_launch(void* const* d_in, const int* in_sizes, int n_in,
                              void* d_out, int out_size)
{
    const float* x     = (const float*)d_in[0];
    const float* W_in  = (const float*)d_in[1];
    const float* b_in  = (const float*)d_in[2];
    const float* W_mid = (const float*)d_in[3];
    const float* b_mid = (const float*)d_in[4];
    const float* W_out = (const float*)d_in[5];
    const float* b_out = (const float*)d_in[6];
    float* out = (float*)d_out;

    const int n = in_sizes[0] / 2;   // x is (N, 2)
    const int threads = 256;
    const int blocks  = (n + threads - 1) / threads;
    pde_mlp_kernel<<<blocks, threads>>>(x, W_in, b_in, W_mid, b_mid,
                                        W_out, b_out, out, n);
}